// round 1
// baseline (speedup 1.0000x reference)
#include <cuda_runtime.h>
#include <cstdint>
#include <math.h>

// Problem dims (fixed by the dataset)
#define T_ 4
#define B_ 32
#define L_ 196
#define D_ 384
#define H_ 1536
#define M_ (T_ * B_ * L_)            // 25088 rows, = 196 * 128
#define SPLITS 64
#define ROWS_PER_SPLIT (M_ / SPLITS) // 392

// ---------------------------------------------------------------------------
// Scratch (device globals; no allocations allowed)
// ---------------------------------------------------------------------------
__device__ float         g_y1[M_ * H_];   // GEMM1 output  (154 MB)
__device__ unsigned char g_sp[M_ * H_];   // layer-1 spikes as u8 (38.5 MB)
__device__ float         g_y2[M_ * D_];   // GEMM2 output  (38.5 MB)
__device__ double        g_psum[SPLITS * H_];
__device__ double        g_psq [SPLITS * H_];
__device__ float         g_mean1[H_], g_rstd1[H_];
__device__ float         g_mean2[D_], g_rstd2[D_];

// ---------------------------------------------------------------------------
// fp32 SGEMM: C[M,N] = A[M,K] * B[K,N] + bias[N]
// 128x128 block tile, BK=8, 8x8 per thread, register-staged double buffering.
// A may be fp32 or uint8 (exact spike values).
// M_ % 128 == 0, N % 128 == 0, K % 8 == 0 — no guards needed.
// ---------------------------------------------------------------------------
template <int N, int K, bool AU8>
__global__ __launch_bounds__(256)
void gemm_k(const void* __restrict__ Ap, const float* __restrict__ Bp,
            const float* __restrict__ bias, float* __restrict__ C)
{
    constexpr int BM = 128, BN = 128, BK = 8;
    constexpr int KT = K / BK;
    __shared__ float As[2][BK][BM];   // transposed A tile
    __shared__ float Bs[2][BK][BN];

    const int tid = threadIdx.x;
    const int bx  = blockIdx.x;       // N tile
    const int by  = blockIdx.y;       // M tile
    const int tx  = tid & 15;         // 0..15 -> N
    const int ty  = tid >> 4;         // 0..15 -> M

    const float*         __restrict__ Af = (const float*)Ap;
    const unsigned char* __restrict__ Au = (const unsigned char*)Ap;

    // A staging: 256 float4 slots cover 128 rows x 8 k
    const int a_row = tid >> 1;            // 0..127
    const int a_k4  = (tid & 1) * 4;       // 0 or 4
    // B staging: 256 float4 slots cover 8 rows x 128 cols
    const int b_row = tid >> 5;            // 0..7
    const int b_c4  = (tid & 31) * 4;      // 0..124

    const unsigned aM = by * BM + a_row;

    float4 ra, rb;
    float acc[8][8];
#pragma unroll
    for (int i = 0; i < 8; i++)
#pragma unroll
        for (int j = 0; j < 8; j++) acc[i][j] = 0.0f;

    auto g_load = [&](int kt) {
        if (AU8) {
            uchar4 u = *(const uchar4*)(Au + (size_t)aM * K + kt * BK + a_k4);
            ra = make_float4((float)u.x, (float)u.y, (float)u.z, (float)u.w);
        } else {
            ra = *(const float4*)(Af + (size_t)aM * K + kt * BK + a_k4);
        }
        rb = *(const float4*)(Bp + (size_t)(kt * BK + b_row) * N + bx * BN + b_c4);
    };
    auto s_store = [&](int buf) {
        As[buf][a_k4 + 0][a_row] = ra.x;
        As[buf][a_k4 + 1][a_row] = ra.y;
        As[buf][a_k4 + 2][a_row] = ra.z;
        As[buf][a_k4 + 3][a_row] = ra.w;
        *(float4*)&Bs[buf][b_row][b_c4] = rb;
    };

    g_load(0);
    s_store(0);
    __syncthreads();

#pragma unroll 1
    for (int kt = 0; kt < KT; kt++) {
        const int cur = kt & 1;
        if (kt + 1 < KT) g_load(kt + 1);   // issue global loads early
#pragma unroll
        for (int k = 0; k < BK; k++) {
            float a[8], b[8];
            *(float4*)&a[0] = *(const float4*)&As[cur][k][ty * 8];
            *(float4*)&a[4] = *(const float4*)&As[cur][k][ty * 8 + 4];
            *(float4*)&b[0] = *(const float4*)&Bs[cur][k][tx * 8];
            *(float4*)&b[4] = *(const float4*)&Bs[cur][k][tx * 8 + 4];
#pragma unroll
            for (int i = 0; i < 8; i++)
#pragma unroll
                for (int j = 0; j < 8; j++)
                    acc[i][j] = fmaf(a[i], b[j], acc[i][j]);
        }
        if (kt + 1 < KT) {
            s_store(cur ^ 1);   // other buffer: safe, cur^1 not read since last barrier
            __syncthreads();
        }
    }

    // Epilogue: + bias, vectorized store
    const int col = bx * BN + tx * 8;
    float bf[8];
    *(float4*)&bf[0] = *(const float4*)(bias + col);
    *(float4*)&bf[4] = *(const float4*)(bias + col + 4);
#pragma unroll
    for (int i = 0; i < 8; i++) {
        const size_t row = (size_t)(by * BM + ty * 8 + i);
        float4 v0, v1;
        v0.x = acc[i][0] + bf[0]; v0.y = acc[i][1] + bf[1];
        v0.z = acc[i][2] + bf[2]; v0.w = acc[i][3] + bf[3];
        v1.x = acc[i][4] + bf[4]; v1.y = acc[i][5] + bf[5];
        v1.z = acc[i][6] + bf[6]; v1.w = acc[i][7] + bf[7];
        *(float4*)(C + row * N + col)     = v0;
        *(float4*)(C + row * N + col + 4) = v1;
    }
}

// ---------------------------------------------------------------------------
// Per-channel BatchNorm stats: deterministic split-M fp64 reduction
// ---------------------------------------------------------------------------
template <int N>
__global__ void stats_partial_k(const float* __restrict__ Y)
{
    const int c = blockIdx.x * 256 + threadIdx.x;
    if (c >= N) return;
    const int s = blockIdx.y;
    const float* p = Y + (size_t)s * ROWS_PER_SPLIT * N + c;
    double su = 0.0, sq = 0.0;
    for (int r = 0; r < ROWS_PER_SPLIT; r++) {
        const double v = (double)p[(size_t)r * N];
        su += v;
        sq += v * v;
    }
    g_psum[s * N + c] = su;
    g_psq [s * N + c] = sq;
}

template <int N>
__global__ void stats_final_k(float* __restrict__ meanf, float* __restrict__ rstdf)
{
    const int c = blockIdx.x * 256 + threadIdx.x;
    if (c >= N) return;
    double su = 0.0, sq = 0.0;
#pragma unroll 4
    for (int s = 0; s < SPLITS; s++) {
        su += g_psum[s * N + c];
        sq += g_psq [s * N + c];
    }
    const double mean = su / (double)M_;
    const double var  = sq / (double)M_ - mean * mean;
    const float  vf   = (float)var;
    meanf[c] = (float)mean;
    // correctly-rounded fp32 rsqrt(var + eps)
    rstdf[c] = (float)(1.0 / sqrt((double)__fadd_rn(vf, 1e-5f)));
}

// ---------------------------------------------------------------------------
// Fused BatchNorm + multistep LIF (tau=2, v_th=1, hard reset to 0).
// Natural [T,B,L,C] layout: time stride is B_*L_*N elements.
// Elementwise ops use _rn intrinsics in the reference's evaluation order.
// ---------------------------------------------------------------------------
template <int N, bool OUT_U8>
__global__ __launch_bounds__(256)
void lif_k(const float* __restrict__ Y,
           const float* __restrict__ meanf, const float* __restrict__ rstdf,
           const float* __restrict__ gamma, const float* __restrict__ beta,
           void* __restrict__ outp)
{
    const int STR = B_ * L_ * N;
    const int idx = blockIdx.x * 256 + threadIdx.x;
    if (idx >= STR) return;
    const int c = idx % N;
    const float mu = meanf[c], rs = rstdf[c], ga = gamma[c], be = beta[c];

    unsigned char* o8 = (unsigned char*)outp;
    float*         of = (float*)outp;

    float v = 0.0f;
#pragma unroll
    for (int t = 0; t < T_; t++) {
        float y = Y[idx + t * STR];
        // ((y - mean) * rsqrt) * gamma + beta — reference op order
        y = __fadd_rn(__fmul_rn(__fmul_rn(__fsub_rn(y, mu), rs), ga), be);
        // v = v + (y - v)/2
        v = __fadd_rn(v, __fmul_rn(__fsub_rn(y, v), 0.5f));
        const bool s = (v >= 1.0f);           // (v - 1.0 >= 0)
        if (OUT_U8) o8[idx + t * STR] = s ? (unsigned char)1 : (unsigned char)0;
        else        of[idx + t * STR] = s ? 1.0f : 0.0f;
        v = s ? 0.0f : v;                     // hard reset
    }
}

// ---------------------------------------------------------------------------
// Launch
// ---------------------------------------------------------------------------
extern "C" void kernel_launch(void* const* d_in, const int* in_sizes, int n_in,
                              void* d_out, int out_size)
{
    const float* x      = (const float*)d_in[0];
    const float* W1     = (const float*)d_in[1];
    const float* b1     = (const float*)d_in[2];
    const float* gamma1 = (const float*)d_in[3];
    const float* beta1  = (const float*)d_in[4];
    const float* W2     = (const float*)d_in[5];
    const float* b2     = (const float*)d_in[6];
    const float* gamma2 = (const float*)d_in[7];
    const float* beta2  = (const float*)d_in[8];

    void *y1, *sp, *y2, *m1, *r1, *m2, *r2;
    cudaGetSymbolAddress(&y1, g_y1);
    cudaGetSymbolAddress(&sp, g_sp);
    cudaGetSymbolAddress(&y2, g_y2);
    cudaGetSymbolAddress(&m1, g_mean1);
    cudaGetSymbolAddress(&r1, g_rstd1);
    cudaGetSymbolAddress(&m2, g_mean2);
    cudaGetSymbolAddress(&r2, g_rstd2);

    // Layer 1: x[25088,384] @ W1[384,1536]
    gemm_k<H_, D_, false><<<dim3(H_ / 128, M_ / 128), 256>>>(x, W1, b1, (float*)y1);
    stats_partial_k<H_><<<dim3(H_ / 256, SPLITS), 256>>>((const float*)y1);
    stats_final_k<H_><<<H_ / 256, 256>>>((float*)m1, (float*)r1);
    lif_k<H_, true><<<(B_ * L_ * H_) / 256, 256>>>(
        (const float*)y1, (const float*)m1, (const float*)r1, gamma1, beta1, sp);

    // Layer 2: spikes[25088,1536](u8) @ W2[1536,384]
    gemm_k<D_, H_, true><<<dim3(D_ / 128, M_ / 128), 256>>>(sp, W2, b2, (float*)y2);
    stats_partial_k<D_><<<dim3((D_ + 255) / 256, SPLITS), 256>>>((const float*)y2);
    stats_final_k<D_><<<(D_ + 255) / 256, 256>>>((float*)m2, (float*)r2);
    lif_k<D_, false><<<(B_ * L_ * D_) / 256, 256>>>(
        (const float*)y2, (const float*)m2, (const float*)r2, gamma2, beta2, d_out);
}

// round 8
// speedup vs baseline: 1.2363x; 1.2363x over previous
#include <cuda_runtime.h>
#include <cstdint>
#include <math.h>

#define T_ 4
#define B_ 32
#define L_ 196
#define D_ 384
#define H_ 1536
#define M_ (T_ * B_ * L_)            // 25088
#define BL_ (B_ * L_)                // 6272
#define SPLITS 64
#define ROWS_PER_SPLIT (M_ / SPLITS) // 392
#define NW 48                        // mask words per row (1536/32)

// ---------------------------------------------------------------------------
// Scratch (device globals; no allocations allowed)
// ---------------------------------------------------------------------------
__device__ __align__(256) float    g_y1[(size_t)M_ * H_];   // 154 MB
__device__ __align__(256) float    g_y2[(size_t)M_ * D_];   // 38.5 MB
__device__ __align__(256) uint32_t g_mask[(size_t)M_ * NW]; // 4.8 MB spike bitmask
__device__ double g_psum[SPLITS * H_];
__device__ double g_psq [SPLITS * H_];
__device__ float  g_mean1[H_], g_rstd1[H_];
__device__ float  g_mean2[D_], g_rstd2[D_];

// ---------------------------------------------------------------------------
// fp32 SGEMM (R1-verbatim): C[M,N] = A[M,K] * B[K,N] + bias[N]
// 128x128 tile, BK=8, 8x8/thread, register-staged double buffer.
// Per-element accumulation strictly ascending-k.
// ---------------------------------------------------------------------------
template <int N, int K>
__global__ __launch_bounds__(256)
void gemm_k(const float* __restrict__ Af, const float* __restrict__ Bp,
            const float* __restrict__ bias, float* __restrict__ C)
{
    constexpr int BM = 128, BN = 128, BK = 8;
    constexpr int KT = K / BK;
    __shared__ float As[2][BK][BM];
    __shared__ float Bs[2][BK][BN];

    const int tid = threadIdx.x;
    const int bx = blockIdx.x, by = blockIdx.y;
    const int tx = tid & 15, ty = tid >> 4;

    const int a_row = tid >> 1;
    const int a_k4  = (tid & 1) * 4;
    const int b_row = tid >> 5;
    const int b_c4  = (tid & 31) * 4;
    const unsigned aM = by * BM + a_row;

    float4 ra, rb;
    float acc[8][8];
#pragma unroll
    for (int i = 0; i < 8; i++)
#pragma unroll
        for (int j = 0; j < 8; j++) acc[i][j] = 0.0f;

    auto g_load = [&](int kt) {
        ra = *(const float4*)(Af + (size_t)aM * K + kt * BK + a_k4);
        rb = *(const float4*)(Bp + (size_t)(kt * BK + b_row) * N + bx * BN + b_c4);
    };
    auto s_store = [&](int buf) {
        As[buf][a_k4 + 0][a_row] = ra.x;
        As[buf][a_k4 + 1][a_row] = ra.y;
        As[buf][a_k4 + 2][a_row] = ra.z;
        As[buf][a_k4 + 3][a_row] = ra.w;
        *(float4*)&Bs[buf][b_row][b_c4] = rb;
    };

    g_load(0);
    s_store(0);
    __syncthreads();

#pragma unroll 1
    for (int kt = 0; kt < KT; kt++) {
        const int cur = kt & 1;
        if (kt + 1 < KT) g_load(kt + 1);
#pragma unroll
        for (int k = 0; k < BK; k++) {
            float a[8], b[8];
            *(float4*)&a[0] = *(const float4*)&As[cur][k][ty * 8];
            *(float4*)&a[4] = *(const float4*)&As[cur][k][ty * 8 + 4];
            *(float4*)&b[0] = *(const float4*)&Bs[cur][k][tx * 8];
            *(float4*)&b[4] = *(const float4*)&Bs[cur][k][tx * 8 + 4];
#pragma unroll
            for (int i = 0; i < 8; i++)
#pragma unroll
                for (int j = 0; j < 8; j++)
                    acc[i][j] = fmaf(a[i], b[j], acc[i][j]);
        }
        if (kt + 1 < KT) {
            s_store(cur ^ 1);
            __syncthreads();
        }
    }

    const int col = bx * BN + tx * 8;
    float bf[8];
    *(float4*)&bf[0] = *(const float4*)(bias + col);
    *(float4*)&bf[4] = *(const float4*)(bias + col + 4);
#pragma unroll
    for (int i = 0; i < 8; i++) {
        const size_t row = (size_t)(by * BM + ty * 8 + i);
        float4 v0, v1;
        v0.x = acc[i][0] + bf[0]; v0.y = acc[i][1] + bf[1];
        v0.z = acc[i][2] + bf[2]; v0.w = acc[i][3] + bf[3];
        v1.x = acc[i][4] + bf[4]; v1.y = acc[i][5] + bf[5];
        v1.z = acc[i][6] + bf[6]; v1.w = acc[i][7] + bf[7];
        *(float4*)(C + row * N + col)     = v0;
        *(float4*)(C + row * N + col + 4) = v1;
    }
}

// ---------------------------------------------------------------------------
// Sparse GEMM2: y2[r,c] = (sum over active k, ascending, of W2[k,c]) + b2[c]
// BIT-IDENTICAL to the R1 dense chain: fmaf(0,w,acc)==acc and
// fmaf(1,w,acc)==__fadd_rn(acc,w) exactly; both iterate k ascending.
// W2 k-tile [384 x 128] fp32 in smem (192 KB); 4 k-passes; ffs bit-walk.
// ---------------------------------------------------------------------------
#define RPB 128      // rows per block
#define CT  128      // cols per c-tile
#define KTP 384      // k per pass

__global__ __launch_bounds__(512)
void gemm2_sparse_k(const uint32_t* __restrict__ mask,
                    const float* __restrict__ W2,
                    const float* __restrict__ b2,
                    float* __restrict__ Y2)
{
    extern __shared__ float sW[];    // [KTP][CT]
    const int tid = threadIdx.x;
    const int lane = tid & 31, w = tid >> 5;       // 16 warps
    const int ct = blockIdx.x;                     // 0..2
    const int row0 = blockIdx.y * RPB + w * 8;     // 8 rows per warp
    const int c0 = ct * CT + lane * 4;

    float4 acc[8];
#pragma unroll
    for (int r = 0; r < 8; r++) acc[r] = make_float4(0.f, 0.f, 0.f, 0.f);

#pragma unroll 1
    for (int kt = 0; kt < 4; kt++) {
        __syncthreads();   // all warps done reading previous tile
        for (int i = tid; i < KTP * (CT / 4); i += 512) {
            const int k = i / (CT / 4), cc = (i % (CT / 4)) * 4;
            *(float4*)&sW[k * CT + cc] =
                *(const float4*)&W2[(size_t)(kt * KTP + k) * D_ + ct * CT + cc];
        }
        __syncthreads();

#pragma unroll 1
        for (int r = 0; r < 8; r++) {
            const uint32_t* mrow = mask + (size_t)(row0 + r) * NW + kt * 12;
            float4 a = acc[r];
#pragma unroll 1
            for (int wd = 0; wd < 12; wd++) {
                uint32_t m = mrow[wd];                 // uniform → broadcast
                const float* base = sW + wd * 32 * CT + lane * 4;
                while (m) {
                    const int b = __ffs(m) - 1;        // lowest bit = ascending k
                    m &= m - 1;
                    const float4 v = *(const float4*)(base + b * CT);
                    a.x = __fadd_rn(a.x, v.x);
                    a.y = __fadd_rn(a.y, v.y);
                    a.z = __fadd_rn(a.z, v.z);
                    a.w = __fadd_rn(a.w, v.w);
                }
            }
            acc[r] = a;
        }
    }

    const float4 bv = *(const float4*)&b2[c0];
#pragma unroll
    for (int r = 0; r < 8; r++) {
        float4 o;
        o.x = acc[r].x + bv.x; o.y = acc[r].y + bv.y;
        o.z = acc[r].z + bv.z; o.w = acc[r].w + bv.w;
        *(float4*)&Y2[(size_t)(row0 + r) * D_ + c0] = o;
    }
}

// ---------------------------------------------------------------------------
// BatchNorm stats (deterministic split-M fp64) — R1 verbatim
// ---------------------------------------------------------------------------
template <int N>
__global__ void stats_partial_k(const float* __restrict__ Y)
{
    const int c = blockIdx.x * 256 + threadIdx.x;
    if (c >= N) return;
    const int s = blockIdx.y;
    const float* p = Y + (size_t)s * ROWS_PER_SPLIT * N + c;
    double su = 0.0, sq = 0.0;
    for (int r = 0; r < ROWS_PER_SPLIT; r++) {
        const double v = (double)p[(size_t)r * N];
        su += v; sq += v * v;
    }
    g_psum[s * N + c] = su;
    g_psq [s * N + c] = sq;
}

template <int N>
__global__ void stats_final_k(float* __restrict__ meanf, float* __restrict__ rstdf)
{
    const int c = blockIdx.x * 256 + threadIdx.x;
    if (c >= N) return;
    double su = 0.0, sq = 0.0;
#pragma unroll 4
    for (int s = 0; s < SPLITS; s++) { su += g_psum[s * N + c]; sq += g_psq[s * N + c]; }
    const double mean = su / (double)M_;
    const double var  = sq / (double)M_ - mean * mean;
    meanf[c] = (float)mean;
    rstdf[c] = (float)(1.0 / sqrt((double)__fadd_rn((float)var, 1e-5f)));
}

// ---------------------------------------------------------------------------
// Layer-1 BN + LIF → spike BITMASK via ballot (R1 arithmetic, new output form)
// Warp lanes own 32 consecutive channels of one row (H_ % 32 == 0).
// ---------------------------------------------------------------------------
__global__ __launch_bounds__(256)
void lif1_k(const float* __restrict__ Y,
            const float* __restrict__ meanf, const float* __restrict__ rstdf,
            const float* __restrict__ gamma, const float* __restrict__ beta,
            uint32_t* __restrict__ mask)
{
    const int STR = BL_ * H_;
    const int idx = blockIdx.x * 256 + threadIdx.x;
    const int lane = threadIdx.x & 31;
    const int c = idx % H_;
    const int bl = idx / H_;
    const float mu = meanf[c], rs = rstdf[c], ga = gamma[c], be = beta[c];

    float v = 0.0f;
#pragma unroll
    for (int t = 0; t < T_; t++) {
        float y = Y[(size_t)idx + (size_t)t * STR];
        y = __fadd_rn(__fmul_rn(__fmul_rn(__fsub_rn(y, mu), rs), ga), be);
        v = __fadd_rn(v, __fmul_rn(__fsub_rn(y, v), 0.5f));
        const bool s = (v >= 1.0f);
        const uint32_t bm = __ballot_sync(0xFFFFFFFFu, s);
        if (lane == 0)
            mask[(size_t)(t * BL_ + bl) * NW + (c >> 5)] = bm;
        v = s ? 0.0f : v;
    }
}

// ---------------------------------------------------------------------------
// Layer-2 BN + LIF → fp32 spikes to d_out (R1 verbatim)
// ---------------------------------------------------------------------------
__global__ __launch_bounds__(256)
void lif2_k(const float* __restrict__ Y,
            const float* __restrict__ meanf, const float* __restrict__ rstdf,
            const float* __restrict__ gamma, const float* __restrict__ beta,
            float* __restrict__ outp)
{
    const int STR = BL_ * D_;
    const int idx = blockIdx.x * 256 + threadIdx.x;
    if (idx >= STR) return;
    const int c = idx % D_;
    const float mu = meanf[c], rs = rstdf[c], ga = gamma[c], be = beta[c];

    float v = 0.0f;
#pragma unroll
    for (int t = 0; t < T_; t++) {
        float y = Y[(size_t)idx + (size_t)t * STR];
        y = __fadd_rn(__fmul_rn(__fmul_rn(__fsub_rn(y, mu), rs), ga), be);
        v = __fadd_rn(v, __fmul_rn(__fsub_rn(y, v), 0.5f));
        const bool s = (v >= 1.0f);
        outp[(size_t)idx + (size_t)t * STR] = s ? 1.0f : 0.0f;
        v = s ? 0.0f : v;
    }
}

// ---------------------------------------------------------------------------
// Launch
// ---------------------------------------------------------------------------
extern "C" void kernel_launch(void* const* d_in, const int* in_sizes, int n_in,
                              void* d_out, int out_size)
{
    const float* x      = (const float*)d_in[0];
    const float* W1     = (const float*)d_in[1];
    const float* b1     = (const float*)d_in[2];
    const float* gamma1 = (const float*)d_in[3];
    const float* beta1  = (const float*)d_in[4];
    const float* W2     = (const float*)d_in[5];
    const float* b2     = (const float*)d_in[6];
    const float* gamma2 = (const float*)d_in[7];
    const float* beta2  = (const float*)d_in[8];

    void *y1, *y2, *mk, *m1, *r1, *m2, *r2;
    cudaGetSymbolAddress(&y1, g_y1);
    cudaGetSymbolAddress(&y2, g_y2);
    cudaGetSymbolAddress(&mk, g_mask);
    cudaGetSymbolAddress(&m1, g_mean1);
    cudaGetSymbolAddress(&r1, g_rstd1);
    cudaGetSymbolAddress(&m2, g_mean2);
    cudaGetSymbolAddress(&r2, g_rstd2);

    const int SMEM2 = KTP * CT * (int)sizeof(float);   // 196608 B
    cudaFuncSetAttribute(gemm2_sparse_k,
                         cudaFuncAttributeMaxDynamicSharedMemorySize, SMEM2);

    // Layer 1: y1 = x @ W1 + b1 (R1 fp32 GEMM)
    gemm_k<H_, D_><<<dim3(H_ / 128, M_ / 128), 256>>>(x, W1, b1, (float*)y1);
    stats_partial_k<H_><<<dim3(H_ / 256, SPLITS), 256>>>((const float*)y1);
    stats_final_k<H_><<<H_ / 256, 256>>>((float*)m1, (float*)r1);
    lif1_k<<<(BL_ * H_) / 256, 256>>>(
        (const float*)y1, (const float*)m1, (const float*)r1, gamma1, beta1,
        (uint32_t*)mk);

    // Layer 2: y2 = spikes @ W2 + b2 (bit-exact sparse accumulate)
    gemm2_sparse_k<<<dim3(D_ / CT, M_ / RPB), 512, SMEM2>>>(
        (const uint32_t*)mk, W2, b2, (float*)y2);
    stats_partial_k<D_><<<dim3((D_ + 255) / 256, SPLITS), 256>>>((const float*)y2);
    stats_final_k<D_><<<(D_ + 255) / 256, 256>>>((float*)m2, (float*)r2);
    lif2_k<<<(BL_ * D_) / 256, 256>>>(
        (const float*)y2, (const float*)m2, (const float*)r2, gamma2, beta2,
        (float*)d_out);
}

// round 9
// speedup vs baseline: 1.2535x; 1.0139x over previous
#include <cuda_runtime.h>
#include <cstdint>
#include <math.h>

#define T_ 4
#define B_ 32
#define L_ 196
#define D_ 384
#define H_ 1536
#define M_ (T_ * B_ * L_)            // 25088
#define BL_ (B_ * L_)                // 6272
#define SPLITS 64
#define ROWS_PER_SPLIT (M_ / SPLITS) // 392
#define NW 48                        // mask words per row (1536/32)

// ---------------------------------------------------------------------------
// Scratch (device globals; no allocations allowed)
// ---------------------------------------------------------------------------
__device__ __align__(256) float    g_y1[(size_t)M_ * H_];   // 154 MB
__device__ __align__(256) float    g_y2[(size_t)M_ * D_];   // 38.5 MB
__device__ __align__(256) uint32_t g_mask[(size_t)M_ * NW]; // 4.8 MB spike bitmask
__device__ double g_psum[SPLITS * H_];
__device__ double g_psq [SPLITS * H_];
__device__ float  g_mean1[H_], g_rstd1[H_];
__device__ float  g_mean2[D_], g_rstd2[D_];

// ---------------------------------------------------------------------------
// fp32 SGEMM with packed fma.rn.f32x2 (Blackwell FFMA2).
// BIT-IDENTICAL to the R1/R8 scalar chain: each 64-bit accumulator holds two
// output columns; each half is an independent rn-rounded FMA chain with the
// same ascending-k order and the same (a,b) product pairing.
// 128x128 tile, BK=8, 8x8/thread, register-staged double buffer.
// ---------------------------------------------------------------------------
template <int N, int K>
__global__ __launch_bounds__(256)
void gemm_k(const float* __restrict__ Af, const float* __restrict__ Bp,
            const float* __restrict__ bias, float* __restrict__ C)
{
    constexpr int BM = 128, BN = 128, BK = 8;
    constexpr int KT = K / BK;
    __shared__ float As[2][BK][BM];
    __shared__ __align__(16) float Bs[2][BK][BN];

    const int tid = threadIdx.x;
    const int bx = blockIdx.x, by = blockIdx.y;
    const int tx = tid & 15, ty = tid >> 4;

    const int a_row = tid >> 1;
    const int a_k4  = (tid & 1) * 4;
    const int b_row = tid >> 5;
    const int b_c4  = (tid & 31) * 4;
    const unsigned aM = by * BM + a_row;

    float4 ra, rb;
    unsigned long long acc2[8][4];   // [mi][cj] = columns (2cj, 2cj+1) packed
#pragma unroll
    for (int i = 0; i < 8; i++)
#pragma unroll
        for (int j = 0; j < 4; j++) acc2[i][j] = 0ULL;

    auto g_load = [&](int kt) {
        ra = *(const float4*)(Af + (size_t)aM * K + kt * BK + a_k4);
        rb = *(const float4*)(Bp + (size_t)(kt * BK + b_row) * N + bx * BN + b_c4);
    };
    auto s_store = [&](int buf) {
        As[buf][a_k4 + 0][a_row] = ra.x;
        As[buf][a_k4 + 1][a_row] = ra.y;
        As[buf][a_k4 + 2][a_row] = ra.z;
        As[buf][a_k4 + 3][a_row] = ra.w;
        *(float4*)&Bs[buf][b_row][b_c4] = rb;
    };

    g_load(0);
    s_store(0);
    __syncthreads();

#pragma unroll 1
    for (int kt = 0; kt < KT; kt++) {
        const int cur = kt & 1;
        if (kt + 1 < KT) g_load(kt + 1);
#pragma unroll
        for (int k = 0; k < BK; k++) {
            float a[8];
            *(float4*)&a[0] = *(const float4*)&As[cur][k][ty * 8];
            *(float4*)&a[4] = *(const float4*)&As[cur][k][ty * 8 + 4];
            // b pairs as raw 64-bit lanes (bit-reinterpret only, no fp ops)
            const ulonglong2 t0 = *(const ulonglong2*)&Bs[cur][k][tx * 8];
            const ulonglong2 t1 = *(const ulonglong2*)&Bs[cur][k][tx * 8 + 4];
            unsigned long long bd[4];
            bd[0] = t0.x; bd[1] = t0.y; bd[2] = t1.x; bd[3] = t1.y;
#pragma unroll
            for (int i = 0; i < 8; i++) {
                unsigned long long ad;
                asm("mov.b64 %0, {%1, %1};" : "=l"(ad) : "f"(a[i]));
#pragma unroll
                for (int j = 0; j < 4; j++)
                    asm("fma.rn.f32x2 %0, %1, %2, %3;"
                        : "=l"(acc2[i][j])
                        : "l"(ad), "l"(bd[j]), "l"(acc2[i][j]));
            }
        }
        if (kt + 1 < KT) {
            s_store(cur ^ 1);
            __syncthreads();
        }
    }

    const int col = bx * BN + tx * 8;
    float bf[8];
    *(float4*)&bf[0] = *(const float4*)(bias + col);
    *(float4*)&bf[4] = *(const float4*)(bias + col + 4);
#pragma unroll
    for (int i = 0; i < 8; i++) {
        const size_t row = (size_t)(by * BM + ty * 8 + i);
        float o[8];
#pragma unroll
        for (int j = 0; j < 4; j++)
            asm("mov.b64 {%0, %1}, %2;"
                : "=f"(o[2 * j]), "=f"(o[2 * j + 1]) : "l"(acc2[i][j]));
        float4 v0, v1;
        v0.x = o[0] + bf[0]; v0.y = o[1] + bf[1];
        v0.z = o[2] + bf[2]; v0.w = o[3] + bf[3];
        v1.x = o[4] + bf[4]; v1.y = o[5] + bf[5];
        v1.z = o[6] + bf[6]; v1.w = o[7] + bf[7];
        *(float4*)(C + row * N + col)     = v0;
        *(float4*)(C + row * N + col + 4) = v1;
    }
}

// ---------------------------------------------------------------------------
// Sparse GEMM2 (R8 verbatim): y2[r,c] = sum over active k (ascending) W2[k,c]
// + b2[c]; bit-identical to the dense fp32 chain.
// ---------------------------------------------------------------------------
#define RPB 128      // rows per block
#define CT  128      // cols per c-tile
#define KTP 384      // k per pass

__global__ __launch_bounds__(512)
void gemm2_sparse_k(const uint32_t* __restrict__ mask,
                    const float* __restrict__ W2,
                    const float* __restrict__ b2,
                    float* __restrict__ Y2)
{
    extern __shared__ float sW[];    // [KTP][CT]
    const int tid = threadIdx.x;
    const int lane = tid & 31, w = tid >> 5;       // 16 warps
    const int ct = blockIdx.x;                     // 0..2
    const int row0 = blockIdx.y * RPB + w * 8;     // 8 rows per warp
    const int c0 = ct * CT + lane * 4;

    float4 acc[8];
#pragma unroll
    for (int r = 0; r < 8; r++) acc[r] = make_float4(0.f, 0.f, 0.f, 0.f);

#pragma unroll 1
    for (int kt = 0; kt < 4; kt++) {
        __syncthreads();
        for (int i = tid; i < KTP * (CT / 4); i += 512) {
            const int k = i / (CT / 4), cc = (i % (CT / 4)) * 4;
            *(float4*)&sW[k * CT + cc] =
                *(const float4*)&W2[(size_t)(kt * KTP + k) * D_ + ct * CT + cc];
        }
        __syncthreads();

#pragma unroll 1
        for (int r = 0; r < 8; r++) {
            const uint32_t* mrow = mask + (size_t)(row0 + r) * NW + kt * 12;
            float4 a = acc[r];
#pragma unroll 1
            for (int wd = 0; wd < 12; wd++) {
                uint32_t m = mrow[wd];
                const float* base = sW + wd * 32 * CT + lane * 4;
                while (m) {
                    const int b = __ffs(m) - 1;
                    m &= m - 1;
                    const float4 v = *(const float4*)(base + b * CT);
                    a.x = __fadd_rn(a.x, v.x);
                    a.y = __fadd_rn(a.y, v.y);
                    a.z = __fadd_rn(a.z, v.z);
                    a.w = __fadd_rn(a.w, v.w);
                }
            }
            acc[r] = a;
        }
    }

    const float4 bv = *(const float4*)&b2[c0];
#pragma unroll
    for (int r = 0; r < 8; r++) {
        float4 o;
        o.x = acc[r].x + bv.x; o.y = acc[r].y + bv.y;
        o.z = acc[r].z + bv.z; o.w = acc[r].w + bv.w;
        *(float4*)&Y2[(size_t)(row0 + r) * D_ + c0] = o;
    }
}

// ---------------------------------------------------------------------------
// BatchNorm stats (deterministic split-M fp64) — R1 verbatim
// ---------------------------------------------------------------------------
template <int N>
__global__ void stats_partial_k(const float* __restrict__ Y)
{
    const int c = blockIdx.x * 256 + threadIdx.x;
    if (c >= N) return;
    const int s = blockIdx.y;
    const float* p = Y + (size_t)s * ROWS_PER_SPLIT * N + c;
    double su = 0.0, sq = 0.0;
    for (int r = 0; r < ROWS_PER_SPLIT; r++) {
        const double v = (double)p[(size_t)r * N];
        su += v; sq += v * v;
    }
    g_psum[s * N + c] = su;
    g_psq [s * N + c] = sq;
}

template <int N>
__global__ void stats_final_k(float* __restrict__ meanf, float* __restrict__ rstdf)
{
    const int c = blockIdx.x * 256 + threadIdx.x;
    if (c >= N) return;
    double su = 0.0, sq = 0.0;
#pragma unroll 4
    for (int s = 0; s < SPLITS; s++) { su += g_psum[s * N + c]; sq += g_psq[s * N + c]; }
    const double mean = su / (double)M_;
    const double var  = sq / (double)M_ - mean * mean;
    meanf[c] = (float)mean;
    rstdf[c] = (float)(1.0 / sqrt((double)__fadd_rn((float)var, 1e-5f)));
}

// ---------------------------------------------------------------------------
// Layer-1 BN + LIF → spike bitmask via ballot (R8 verbatim)
// ---------------------------------------------------------------------------
__global__ __launch_bounds__(256)
void lif1_k(const float* __restrict__ Y,
            const float* __restrict__ meanf, const float* __restrict__ rstdf,
            const float* __restrict__ gamma, const float* __restrict__ beta,
            uint32_t* __restrict__ mask)
{
    const int STR = BL_ * H_;
    const int idx = blockIdx.x * 256 + threadIdx.x;
    const int lane = threadIdx.x & 31;
    const int c = idx % H_;
    const int bl = idx / H_;
    const float mu = meanf[c], rs = rstdf[c], ga = gamma[c], be = beta[c];

    float v = 0.0f;
#pragma unroll
    for (int t = 0; t < T_; t++) {
        float y = Y[(size_t)idx + (size_t)t * STR];
        y = __fadd_rn(__fmul_rn(__fmul_rn(__fsub_rn(y, mu), rs), ga), be);
        v = __fadd_rn(v, __fmul_rn(__fsub_rn(y, v), 0.5f));
        const bool s = (v >= 1.0f);
        const uint32_t bm = __ballot_sync(0xFFFFFFFFu, s);
        if (lane == 0)
            mask[(size_t)(t * BL_ + bl) * NW + (c >> 5)] = bm;
        v = s ? 0.0f : v;
    }
}

// ---------------------------------------------------------------------------
// Layer-2 BN + LIF → fp32 spikes to d_out (R8 verbatim)
// ---------------------------------------------------------------------------
__global__ __launch_bounds__(256)
void lif2_k(const float* __restrict__ Y,
            const float* __restrict__ meanf, const float* __restrict__ rstdf,
            const float* __restrict__ gamma, const float* __restrict__ beta,
            float* __restrict__ outp)
{
    const int STR = BL_ * D_;
    const int idx = blockIdx.x * 256 + threadIdx.x;
    if (idx >= STR) return;
    const int c = idx % D_;
    const float mu = meanf[c], rs = rstdf[c], ga = gamma[c], be = beta[c];

    float v = 0.0f;
#pragma unroll
    for (int t = 0; t < T_; t++) {
        float y = Y[(size_t)idx + (size_t)t * STR];
        y = __fadd_rn(__fmul_rn(__fmul_rn(__fsub_rn(y, mu), rs), ga), be);
        v = __fadd_rn(v, __fmul_rn(__fsub_rn(y, v), 0.5f));
        const bool s = (v >= 1.0f);
        outp[(size_t)idx + (size_t)t * STR] = s ? 1.0f : 0.0f;
        v = s ? 0.0f : v;
    }
}

// ---------------------------------------------------------------------------
// Launch
// ---------------------------------------------------------------------------
extern "C" void kernel_launch(void* const* d_in, const int* in_sizes, int n_in,
                              void* d_out, int out_size)
{
    const float* x      = (const float*)d_in[0];
    const float* W1     = (const float*)d_in[1];
    const float* b1     = (const float*)d_in[2];
    const float* gamma1 = (const float*)d_in[3];
    const float* beta1  = (const float*)d_in[4];
    const float* W2     = (const float*)d_in[5];
    const float* b2     = (const float*)d_in[6];
    const float* gamma2 = (const float*)d_in[7];
    const float* beta2  = (const float*)d_in[8];

    void *y1, *y2, *mk, *m1, *r1, *m2, *r2;
    cudaGetSymbolAddress(&y1, g_y1);
    cudaGetSymbolAddress(&y2, g_y2);
    cudaGetSymbolAddress(&mk, g_mask);
    cudaGetSymbolAddress(&m1, g_mean1);
    cudaGetSymbolAddress(&r1, g_rstd1);
    cudaGetSymbolAddress(&m2, g_mean2);
    cudaGetSymbolAddress(&r2, g_rstd2);

    const int SMEM2 = KTP * CT * (int)sizeof(float);   // 196608 B
    cudaFuncSetAttribute(gemm2_sparse_k,
                         cudaFuncAttributeMaxDynamicSharedMemorySize, SMEM2);

    // Layer 1: y1 = x @ W1 + b1 (f32x2 FFMA2 GEMM, bit-identical to R8)
    gemm_k<H_, D_><<<dim3(H_ / 128, M_ / 128), 256>>>(x, W1, b1, (float*)y1);
    stats_partial_k<H_><<<dim3(H_ / 256, SPLITS), 256>>>((const float*)y1);
    stats_final_k<H_><<<H_ / 256, 256>>>((float*)m1, (float*)r1);
    lif1_k<<<(BL_ * H_) / 256, 256>>>(
        (const float*)y1, (const float*)m1, (const float*)r1, gamma1, beta1,
        (uint32_t*)mk);

    // Layer 2: y2 = spikes @ W2 + b2 (bit-exact sparse accumulate)
    gemm2_sparse_k<<<dim3(D_ / CT, M_ / RPB), 512, SMEM2>>>(
        (const uint32_t*)mk, W2, b2, (float*)y2);
    stats_partial_k<D_><<<dim3((D_ + 255) / 256, SPLITS), 256>>>((const float*)y2);
    stats_final_k<D_><<<(D_ + 255) / 256, 256>>>((float*)m2, (float*)r2);
    lif2_k<<<(BL_ * D_) / 256, 256>>>(
        (const float*)y2, (const float*)m2, (const float*)r2, gamma2, beta2,
        (float*)d_out);
}

// round 10
// speedup vs baseline: 1.6024x; 1.2783x over previous
#include <cuda_runtime.h>
#include <cstdint>
#include <math.h>

#define T_ 4
#define B_ 32
#define L_ 196
#define D_ 384
#define H_ 1536
#define M_ (T_ * B_ * L_)            // 25088
#define BL_ (B_ * L_)                // 6272
#define SPLITS 196                   // one split per 128-row tile
#define NW 48                        // mask words per row (1536/32)

// ---------------------------------------------------------------------------
// Scratch (device globals; no allocations allowed)
// ---------------------------------------------------------------------------
__device__ __align__(256) float    g_y1[(size_t)M_ * H_];   // 154 MB
__device__ __align__(256) float    g_y2[(size_t)M_ * D_];   // 38.5 MB
__device__ __align__(256) uint32_t g_mask[(size_t)M_ * NW]; // 4.8 MB spike bitmask
__device__ double g_psum[SPLITS * H_];
__device__ double g_psq [SPLITS * H_];
__device__ float  g_mean1[H_], g_rstd1[H_];
__device__ float  g_mean2[D_], g_rstd2[D_];

__global__ void nop_k() {}   // profile-slot alignment

// ---------------------------------------------------------------------------
// fp32 SGEMM (R9-verbatim math) + fused per-tile BN-stat partials.
// Each CTA emits fp64 (sum, sumsq) partials for its 128 rows x 128 cols:
// fp32 over the 8 in-register rows (fixed order), fp64 across the 16 ty
// threads (ascending). stats_final sums the 196 splits ascending.
// ---------------------------------------------------------------------------
template <int N, int K>
__global__ __launch_bounds__(256)
void gemm_k(const float* __restrict__ Af, const float* __restrict__ Bp,
            const float* __restrict__ bias, float* __restrict__ C)
{
    constexpr int BM = 128, BN = 128, BK = 8;
    constexpr int KT = K / BK;
    __shared__ float As[2][BK][BM];
    __shared__ __align__(16) float Bs[2][BK][BN];
    __shared__ float sSU[16][128];
    __shared__ float sSQ[16][128];

    const int tid = threadIdx.x;
    const int bx = blockIdx.x, by = blockIdx.y;
    const int tx = tid & 15, ty = tid >> 4;

    const int a_row = tid >> 1;
    const int a_k4  = (tid & 1) * 4;
    const int b_row = tid >> 5;
    const int b_c4  = (tid & 31) * 4;
    const unsigned aM = by * BM + a_row;

    float4 ra, rb;
    unsigned long long acc2[8][4];
#pragma unroll
    for (int i = 0; i < 8; i++)
#pragma unroll
        for (int j = 0; j < 4; j++) acc2[i][j] = 0ULL;

    auto g_load = [&](int kt) {
        ra = *(const float4*)(Af + (size_t)aM * K + kt * BK + a_k4);
        rb = *(const float4*)(Bp + (size_t)(kt * BK + b_row) * N + bx * BN + b_c4);
    };
    auto s_store = [&](int buf) {
        As[buf][a_k4 + 0][a_row] = ra.x;
        As[buf][a_k4 + 1][a_row] = ra.y;
        As[buf][a_k4 + 2][a_row] = ra.z;
        As[buf][a_k4 + 3][a_row] = ra.w;
        *(float4*)&Bs[buf][b_row][b_c4] = rb;
    };

    g_load(0);
    s_store(0);
    __syncthreads();

#pragma unroll 1
    for (int kt = 0; kt < KT; kt++) {
        const int cur = kt & 1;
        if (kt + 1 < KT) g_load(kt + 1);
#pragma unroll
        for (int k = 0; k < BK; k++) {
            float a[8];
            *(float4*)&a[0] = *(const float4*)&As[cur][k][ty * 8];
            *(float4*)&a[4] = *(const float4*)&As[cur][k][ty * 8 + 4];
            const ulonglong2 t0 = *(const ulonglong2*)&Bs[cur][k][tx * 8];
            const ulonglong2 t1 = *(const ulonglong2*)&Bs[cur][k][tx * 8 + 4];
            unsigned long long bd[4];
            bd[0] = t0.x; bd[1] = t0.y; bd[2] = t1.x; bd[3] = t1.y;
#pragma unroll
            for (int i = 0; i < 8; i++) {
                unsigned long long ad;
                asm("mov.b64 %0, {%1, %1};" : "=l"(ad) : "f"(a[i]));
#pragma unroll
                for (int j = 0; j < 4; j++)
                    asm("fma.rn.f32x2 %0, %1, %2, %3;"
                        : "=l"(acc2[i][j])
                        : "l"(ad), "l"(bd[j]), "l"(acc2[i][j]));
            }
        }
        if (kt + 1 < KT) {
            s_store(cur ^ 1);
            __syncthreads();
        }
    }

    const int col = bx * BN + tx * 8;
    float bf[8];
    *(float4*)&bf[0] = *(const float4*)(bias + col);
    *(float4*)&bf[4] = *(const float4*)(bias + col + 4);

    // pass 1: store y (bit-identical to R9)
#pragma unroll
    for (int i = 0; i < 8; i++) {
        const size_t row = (size_t)(by * BM + ty * 8 + i);
        float o[8];
#pragma unroll
        for (int j = 0; j < 4; j++)
            asm("mov.b64 {%0, %1}, %2;"
                : "=f"(o[2 * j]), "=f"(o[2 * j + 1]) : "l"(acc2[i][j]));
        float4 v0, v1;
        v0.x = o[0] + bf[0]; v0.y = o[1] + bf[1];
        v0.z = o[2] + bf[2]; v0.w = o[3] + bf[3];
        v1.x = o[4] + bf[4]; v1.y = o[5] + bf[5];
        v1.z = o[6] + bf[6]; v1.w = o[7] + bf[7];
        *(float4*)(C + row * N + col)     = v0;
        *(float4*)(C + row * N + col + 4) = v1;
    }

    // pass 2: fused stat partials (reg-light, col-at-a-time)
#pragma unroll
    for (int j = 0; j < 8; j++) {
        float su = 0.0f, sq = 0.0f;
#pragma unroll
        for (int i = 0; i < 8; i++) {
            float lo, hi;
            asm("mov.b64 {%0, %1}, %2;" : "=f"(lo), "=f"(hi) : "l"(acc2[i][j >> 1]));
            const float o = ((j & 1) ? hi : lo) + bf[j];
            su += o;
            sq = fmaf(o, o, sq);
        }
        sSU[ty][tx * 8 + j] = su;
        sSQ[ty][tx * 8 + j] = sq;
    }
    __syncthreads();
    if (tid < 128) {
        double s = 0.0, q = 0.0;
#pragma unroll
        for (int u = 0; u < 16; u++) {
            s += (double)sSU[u][tid];
            q += (double)sSQ[u][tid];
        }
        g_psum[(size_t)by * N + bx * BN + tid] = s;
        g_psq [(size_t)by * N + bx * BN + tid] = q;
    }
}

// ---------------------------------------------------------------------------
// Sparse GEMM2 (R8/R9-verbatim math) + fused per-tile BN-stat partials.
// ---------------------------------------------------------------------------
#define RPB 128
#define CT  128
#define KTP 384

__global__ __launch_bounds__(512)
void gemm2_sparse_k(const uint32_t* __restrict__ mask,
                    const float* __restrict__ W2,
                    const float* __restrict__ b2,
                    float* __restrict__ Y2)
{
    extern __shared__ float sW[];    // [KTP][CT] then stats area [2][16][128]
    float* sS = sW + KTP * CT;
    const int tid = threadIdx.x;
    const int lane = tid & 31, w = tid >> 5;
    const int ct = blockIdx.x;
    const int row0 = blockIdx.y * RPB + w * 8;
    const int c0 = ct * CT + lane * 4;

    float4 acc[8];
#pragma unroll
    for (int r = 0; r < 8; r++) acc[r] = make_float4(0.f, 0.f, 0.f, 0.f);

#pragma unroll 1
    for (int kt = 0; kt < 4; kt++) {
        __syncthreads();
        for (int i = tid; i < KTP * (CT / 4); i += 512) {
            const int k = i / (CT / 4), cc = (i % (CT / 4)) * 4;
            *(float4*)&sW[k * CT + cc] =
                *(const float4*)&W2[(size_t)(kt * KTP + k) * D_ + ct * CT + cc];
        }
        __syncthreads();

#pragma unroll 1
        for (int r = 0; r < 8; r++) {
            const uint32_t* mrow = mask + (size_t)(row0 + r) * NW + kt * 12;
            float4 a = acc[r];
#pragma unroll 1
            for (int wd = 0; wd < 12; wd++) {
                uint32_t m = mrow[wd];
                const float* base = sW + wd * 32 * CT + lane * 4;
                while (m) {
                    const int b = __ffs(m) - 1;
                    m &= m - 1;
                    const float4 v = *(const float4*)(base + b * CT);
                    a.x = __fadd_rn(a.x, v.x);
                    a.y = __fadd_rn(a.y, v.y);
                    a.z = __fadd_rn(a.z, v.z);
                    a.w = __fadd_rn(a.w, v.w);
                }
            }
            acc[r] = a;
        }
    }

    const float4 bv = *(const float4*)&b2[c0];
    float4 su = make_float4(0.f, 0.f, 0.f, 0.f);
    float4 sq = make_float4(0.f, 0.f, 0.f, 0.f);
#pragma unroll
    for (int r = 0; r < 8; r++) {
        float4 o;
        o.x = acc[r].x + bv.x; o.y = acc[r].y + bv.y;
        o.z = acc[r].z + bv.z; o.w = acc[r].w + bv.w;
        *(float4*)&Y2[(size_t)(row0 + r) * D_ + c0] = o;
        su.x += o.x; sq.x = fmaf(o.x, o.x, sq.x);
        su.y += o.y; sq.y = fmaf(o.y, o.y, sq.y);
        su.z += o.z; sq.z = fmaf(o.z, o.z, sq.z);
        su.w += o.w; sq.w = fmaf(o.w, o.w, sq.w);
    }
    // stats partials: [0..2047] su, [2048..4095] sq
    *(float4*)&sS[w * 128 + lane * 4]        = su;
    *(float4*)&sS[2048 + w * 128 + lane * 4] = sq;
    __syncthreads();
    if (tid < 128) {
        double s = 0.0, q = 0.0;
#pragma unroll
        for (int u = 0; u < 16; u++) {
            s += (double)sS[u * 128 + tid];
            q += (double)sS[2048 + u * 128 + tid];
        }
        g_psum[(size_t)blockIdx.y * D_ + ct * CT + tid] = s;
        g_psq [(size_t)blockIdx.y * D_ + ct * CT + tid] = q;
    }
}

// ---------------------------------------------------------------------------
// Final stats: fp64 sum over 196 splits (ascending, deterministic)
// ---------------------------------------------------------------------------
template <int N>
__global__ void stats_final_k(float* __restrict__ meanf, float* __restrict__ rstdf)
{
    const int c = blockIdx.x * 256 + threadIdx.x;
    if (c >= N) return;
    double su = 0.0, sq = 0.0;
#pragma unroll 4
    for (int s = 0; s < SPLITS; s++) { su += g_psum[s * N + c]; sq += g_psq[s * N + c]; }
    const double mean = su / (double)M_;
    const double var  = sq / (double)M_ - mean * mean;
    meanf[c] = (float)mean;
    rstdf[c] = (float)(1.0 / sqrt((double)__fadd_rn((float)var, 1e-5f)));
}

// ---------------------------------------------------------------------------
// Layer-1 BN + LIF → spike bitmask via ballot (R8 verbatim)
// ---------------------------------------------------------------------------
__global__ __launch_bounds__(256)
void lif1_k(const float* __restrict__ Y,
            const float* __restrict__ meanf, const float* __restrict__ rstdf,
            const float* __restrict__ gamma, const float* __restrict__ beta,
            uint32_t* __restrict__ mask)
{
    const int STR = BL_ * H_;
    const int idx = blockIdx.x * 256 + threadIdx.x;
    const int lane = threadIdx.x & 31;
    const int c = idx % H_;
    const int bl = idx / H_;
    const float mu = meanf[c], rs = rstdf[c], ga = gamma[c], be = beta[c];

    float v = 0.0f;
#pragma unroll
    for (int t = 0; t < T_; t++) {
        float y = Y[(size_t)idx + (size_t)t * STR];
        y = __fadd_rn(__fmul_rn(__fmul_rn(__fsub_rn(y, mu), rs), ga), be);
        v = __fadd_rn(v, __fmul_rn(__fsub_rn(y, v), 0.5f));
        const bool s = (v >= 1.0f);
        const uint32_t bm = __ballot_sync(0xFFFFFFFFu, s);
        if (lane == 0)
            mask[(size_t)(t * BL_ + bl) * NW + (c >> 5)] = bm;
        v = s ? 0.0f : v;
    }
}

// ---------------------------------------------------------------------------
// Layer-2 BN + LIF → fp32 spikes to d_out (R8 verbatim)
// ---------------------------------------------------------------------------
__global__ __launch_bounds__(256)
void lif2_k(const float* __restrict__ Y,
            const float* __restrict__ meanf, const float* __restrict__ rstdf,
            const float* __restrict__ gamma, const float* __restrict__ beta,
            float* __restrict__ outp)
{
    const int STR = BL_ * D_;
    const int idx = blockIdx.x * 256 + threadIdx.x;
    if (idx >= STR) return;
    const int c = idx % D_;
    const float mu = meanf[c], rs = rstdf[c], ga = gamma[c], be = beta[c];

    float v = 0.0f;
#pragma unroll
    for (int t = 0; t < T_; t++) {
        float y = Y[(size_t)idx + (size_t)t * STR];
        y = __fadd_rn(__fmul_rn(__fmul_rn(__fsub_rn(y, mu), rs), ga), be);
        v = __fadd_rn(v, __fmul_rn(__fsub_rn(y, v), 0.5f));
        const bool s = (v >= 1.0f);
        outp[(size_t)idx + (size_t)t * STR] = s ? 1.0f : 0.0f;
        v = s ? 0.0f : v;
    }
}

// ---------------------------------------------------------------------------
// Launch
// ---------------------------------------------------------------------------
extern "C" void kernel_launch(void* const* d_in, const int* in_sizes, int n_in,
                              void* d_out, int out_size)
{
    const float* x      = (const float*)d_in[0];
    const float* W1     = (const float*)d_in[1];
    const float* b1     = (const float*)d_in[2];
    const float* gamma1 = (const float*)d_in[3];
    const float* beta1  = (const float*)d_in[4];
    const float* W2     = (const float*)d_in[5];
    const float* b2     = (const float*)d_in[6];
    const float* gamma2 = (const float*)d_in[7];
    const float* beta2  = (const float*)d_in[8];

    void *y1, *y2, *mk, *m1, *r1, *m2, *r2;
    cudaGetSymbolAddress(&y1, g_y1);
    cudaGetSymbolAddress(&y2, g_y2);
    cudaGetSymbolAddress(&mk, g_mask);
    cudaGetSymbolAddress(&m1, g_mean1);
    cudaGetSymbolAddress(&r1, g_rstd1);
    cudaGetSymbolAddress(&m2, g_mean2);
    cudaGetSymbolAddress(&r2, g_rstd2);

    const int SMEM2 = (KTP * CT + 4096) * (int)sizeof(float);   // 212992 B
    cudaFuncSetAttribute(gemm2_sparse_k,
                         cudaFuncAttributeMaxDynamicSharedMemorySize, SMEM2);

    // align ncu capture slot onto gemm_k
    nop_k<<<1, 1>>>();
    nop_k<<<1, 1>>>();
    nop_k<<<1, 1>>>();

    // Layer 1
    gemm_k<H_, D_><<<dim3(H_ / 128, M_ / 128), 256>>>(x, W1, b1, (float*)y1);
    stats_final_k<H_><<<H_ / 256, 256>>>((float*)m1, (float*)r1);
    lif1_k<<<(BL_ * H_) / 256, 256>>>(
        (const float*)y1, (const float*)m1, (const float*)r1, gamma1, beta1,
        (uint32_t*)mk);

    // Layer 2
    gemm2_sparse_k<<<dim3(D_ / CT, M_ / RPB), 512, SMEM2>>>(
        (const uint32_t*)mk, W2, b2, (float*)y2);
    stats_final_k<D_><<<(D_ + 255) / 256, 256>>>((float*)m2, (float*)r2);
    lif2_k<<<(BL_ * D_) / 256, 256>>>(
        (const float*)y2, (const float*)m2, (const float*)r2, gamma2, beta2,
        (float*)d_out);
}